// round 12
// baseline (speedup 1.0000x reference)
#include <cuda_runtime.h>

#define NUM_LABELS 51
#define CH 16
#define SPATIAL (32 * 256 * 256)   // 2097152 = 1<<21
#define NVOX (2 * SPATIAL)         // 4194304
#define EPSF 1e-8f

#define V 512            // voxels per tile (8192 tiles)
#define VPT 2            // voxels per thread per tile (256 threads)
#define STRIDEF 16       // floats per entry (16 channels, rinv reconstructed)
#define NBLK 444         // 148 SMs x 3 blocks (64KB+ dyn smem each)
#define NTILES (NVOX / V)

// dynamic smem layout: [ buf0 | buf1 | hist[2][51] | base[2][51] ]
#define SMEM_FLOATS (2 * V * STRIDEF)
#define SMEM_BYTES  (SMEM_FLOATS * 4 + 4 * 51 * 4)

// Per-block partial outputs (fully overwritten every launch)
__device__ float g_psum [NBLK][50 * CH];
__device__ float g_pnsum[NBLK][50 * CH];
__device__ float g_pcnt [NBLK][50];

__device__ __forceinline__ void cp4(unsigned dst, const float* src) {
    asm volatile("cp.async.ca.shared.global [%0], [%1], 4;" :: "r"(dst), "l"(src));
}

__global__ __launch_bounds__(256) void k_main(const float* __restrict__ pred,
                                              const int* __restrict__ gt) {
    extern __shared__ __align__(16) float s_raw[];
    float* s_buf[2] = { s_raw, s_raw + V * STRIDEF };
    int* s_hist = (int*)(s_raw + SMEM_FLOATS);   // [2][51]
    int* s_base = s_hist + 2 * 51;               // [2][51]

    const int tid  = threadIdx.x;
    const int lane = tid & 31;
    const unsigned cmask = 0xFu << (lane & 28);  // 4-lane cluster mask

    float4 aS = make_float4(0.f, 0.f, 0.f, 0.f);
    float4 aN = make_float4(0.f, 0.f, 0.f, 0.f);
    int cntAcc = 0;

    for (int i = tid; i < 2 * NUM_LABELS; i += 256) s_hist[i] = 0;
    __syncthreads();

    int rbaseC = 0, rcntC = 0;   // reduce params for in-flight tile
    int p = 0;
    int iter = 0;

    for (int tile = blockIdx.x; tile < NTILES; tile += gridDim.x, iter++) {
        int n0 = tile * V;
        int* hist = s_hist + p * NUM_LABELS;
        int* base = s_base + p * NUM_LABELS;

        // ---- B: labels + warp-aggregated ranking ----
        int lab[VPT], rnk[VPT];
        #pragma unroll
        for (int k = 0; k < VPT; k++) {
            int n = n0 + tid + k * 256;
            int l = gt[n];
            bool valid = ((unsigned)(l - 1) <= 49u);
            int lv = valid ? l : -1;
            unsigned mask = __match_any_sync(0xffffffffu, lv);
            int leader = __ffs(mask) - 1;
            int rinw = __popc(mask & ((1u << lane) - 1u));
            int b = 0;
            if (lane == leader && valid) b = atomicAdd(&hist[lv], __popc(mask));
            b = __shfl_sync(0xffffffffu, b, leader);
            lab[k] = lv;
            rnk[k] = b + rinw;
        }
        __syncthreads();

        // ---- C: warp-shuffle exclusive scan over 51 bins (warp 0) ----
        if (tid < 32) {
            int a = (tid < NUM_LABELS) ? hist[tid] : 0;
            int b = (tid + 32 < NUM_LABELS) ? hist[tid + 32] : 0;
            int sa = a, sb = b;
            #pragma unroll
            for (int d = 1; d < 32; d <<= 1) {
                int t1 = __shfl_up_sync(0xffffffffu, sa, d);
                int t2 = __shfl_up_sync(0xffffffffu, sb, d);
                if (lane >= d) { sa += t1; sb += t2; }
            }
            int totA = __shfl_sync(0xffffffffu, sa, 31);
            if (tid < NUM_LABELS) base[tid] = sa - a;
            if (tid + 32 < NUM_LABELS) base[tid + 32] = totA + sb - b;
        }
        if (tid >= 32 && tid < 32 + NUM_LABELS) cntAcc += hist[tid - 32];
        __syncthreads();

        // capture reduce params for THIS tile (used next iteration)
        int rbaseN = 0, rcntN = 0;
        if (tid < 200) {
            int l = (tid >> 2) + 1;
            rbaseN = base[l];
            rcntN  = hist[l];
        }

        // ---- D: async-copy pred -> sorted smem slots (swizzled) ----
        unsigned bufA = (unsigned)__cvta_generic_to_shared(s_buf[p]);
        #pragma unroll
        for (int k = 0; k < VPT; k++) {
            if (lab[k] > 0) {
                int n  = n0 + tid + k * 256;
                int bb = n >> 21;
                int sp = n & (SPATIAL - 1);
                const float* src = pred + ((long)bb << 25) + sp;
                int slot = base[lab[k]] + rnk[k];
                unsigned d0 = bufA + (unsigned)slot * (STRIDEF * 4);
                int rot = slot & 3;
                #pragma unroll
                for (int c = 0; c < CH; c++) {
                    int dstf = ((((c >> 2) + rot) & 3) << 2) | (c & 3);
                    cp4(d0 + dstf * 4, src + ((long)c << 21));
                }
            }
        }
        asm volatile("cp.async.commit_group;");
        asm volatile("cp.async.wait_group 1;");   // previous tile's data landed
        __syncthreads();

        // ---- E: reduce previous tile (buf p^1); idle threads re-zero hist[p] ----
        if (iter > 0) {
            if (tid < 200 && rcntC > 0) {
                int g = tid & 3;
                const float* bufP = s_buf[p ^ 1];
                for (int j = 0; j < rcntC; j++) {
                    int slot = rbaseC + j;
                    const float4 v4 = *(const float4*)(bufP + slot * STRIDEF
                                                       + ((((g + slot) & 3)) << 2));
                    float ssq = v4.x * v4.x + v4.y * v4.y + v4.z * v4.z + v4.w * v4.w;
                    ssq += __shfl_xor_sync(cmask, ssq, 1);
                    ssq += __shfl_xor_sync(cmask, ssq, 2);
                    float ri = rsqrtf(ssq);
                    aS.x += v4.x;      aS.y += v4.y;      aS.z += v4.z;      aS.w += v4.w;
                    aN.x += v4.x * ri; aN.y += v4.y * ri; aN.z += v4.z * ri; aN.w += v4.w * ri;
                }
            }
        }
        if (tid >= 200 && tid - 200 < NUM_LABELS) hist[tid - 200] = 0;  // for tile t+2
        __syncthreads();

        rbaseC = rbaseN; rcntC = rcntN;
        p ^= 1;
    }

    // ---- Epilogue: reduce the last tile ----
    asm volatile("cp.async.wait_group 0;");
    __syncthreads();
    if (iter > 0 && tid < 200 && rcntC > 0) {
        int g = tid & 3;
        const float* bufP = s_buf[p ^ 1];
        for (int j = 0; j < rcntC; j++) {
            int slot = rbaseC + j;
            const float4 v4 = *(const float4*)(bufP + slot * STRIDEF
                                               + ((((g + slot) & 3)) << 2));
            float ssq = v4.x * v4.x + v4.y * v4.y + v4.z * v4.z + v4.w * v4.w;
            ssq += __shfl_xor_sync(cmask, ssq, 1);
            ssq += __shfl_xor_sync(cmask, ssq, 2);
            float ri = rsqrtf(ssq);
            aS.x += v4.x;      aS.y += v4.y;      aS.z += v4.z;      aS.w += v4.w;
            aN.x += v4.x * ri; aN.y += v4.y * ri; aN.z += v4.z * ri; aN.w += v4.w * ri;
        }
    }

    // ---- Flush per-block partials ----
    if (tid < 200) {
        int l0 = tid >> 2;
        int g  = tid & 3;
        int o  = l0 * CH + 4 * g;
        *(float4*)&g_psum [blockIdx.x][o] = aS;
        *(float4*)&g_pnsum[blockIdx.x][o] = aN;
    }
    if (tid >= 33 && tid < 32 + NUM_LABELS)
        g_pcnt[blockIdx.x][tid - 33] = (float)cntAcc;
}

// Merged reduction + finalization: 800 threads, coalesced partial sums.
__global__ __launch_bounds__(800) void k_final(float* __restrict__ out) {
    __shared__ float s_m[800];    // means (then normalized means)
    __shared__ float s_ns[800];   // nsum
    __shared__ float s_c[50];
    __shared__ float s_in[50];
    __shared__ float s_acc[2];
    int tid = threadIdx.x;
    if (tid < 2) s_acc[tid] = 0.f;

    // Stage 1: transposed, coalesced reduction over NBLK partials
    float a = 0.f, b = 0.f;
    #pragma unroll 4
    for (int blk = 0; blk < NBLK; blk++) {
        a += g_psum[blk][tid];
        b += g_pnsum[blk][tid];
    }
    s_ns[tid] = b;
    if (tid < 50) {
        float c = 0.f;
        #pragma unroll 4
        for (int blk = 0; blk < NBLK; blk++) c += g_pcnt[blk][tid];
        s_c[tid] = c;
    }
    __syncthreads();

    s_m[tid] = a / fmaxf(s_c[tid >> 4], 1.f);
    __syncthreads();

    // norms + intra: intra_l = dot(m_l, nsum_l) / (|m_l| * count_l)
    if (tid < 50) {
        float n2 = 0.f;
        #pragma unroll
        for (int c = 0; c < 16; c++) { float m = s_m[tid * 16 + c]; n2 += m * m; }
        float nrm = sqrtf(n2);
        s_in[tid] = 1.f / fmaxf(nrm, EPSF);

        float dot = 0.f;
        #pragma unroll
        for (int c = 0; c < 16; c++) dot += s_m[tid * 16 + c] * s_ns[tid * 16 + c];
        float intra_l = dot / (fmaxf(nrm, 1e-30f) * fmaxf(s_c[tid], 1.f));
        atomicAdd(&s_acc[1], intra_l);
    }
    __syncthreads();

    s_m[tid] *= s_in[tid >> 4];
    __syncthreads();

    float local = 0.f;
    for (int pp = tid; pp < 1225; pp += 800) {
        int i = 0, rem = pp;
        while (rem >= 49 - i) { rem -= 49 - i; i++; }
        int j = i + 1 + rem;
        float dot = 0.f;
        #pragma unroll
        for (int c = 0; c < 16; c++) dot += s_m[i * 16 + c] * s_m[j * 16 + c];
        local += fminf(fmaxf(dot, 0.f), 1.f);
    }
    atomicAdd(&s_acc[0], local);
    __syncthreads();

    if (tid == 0) out[0] = s_acc[0] * (1.f / 1225.f) - s_acc[1] * (1.f / 50.f);
}

extern "C" void kernel_launch(void* const* d_in, const int* in_sizes, int n_in,
                              void* d_out, int out_size) {
    const float* pred = (const float*)d_in[0];
    const int* gt = (const int*)d_in[1];
    float* out = (float*)d_out;

    cudaFuncSetAttribute(k_main, cudaFuncAttributeMaxDynamicSharedMemorySize, SMEM_BYTES);
    k_main<<<NBLK, 256, SMEM_BYTES>>>(pred, gt);
    k_final<<<1, 800>>>(out);
}

// round 13
// speedup vs baseline: 1.7710x; 1.7710x over previous
#include <cuda_runtime.h>

#define NUM_LABELS 51
#define CH 16
#define SPATIAL (1 << 21)          // 32*256*256
#define NVOX (2 * SPATIAL)
#define EPSF 1e-8f

#define V 512                      // voxels per tile (8192 tiles)
#define VPT 2                      // voxels per thread per tile
#define STRIDEW 20                 // words per entry (16 data + 4 pad, bank spread)
#define NBLK 296                   // 148 SMs x 2 blocks
#define NTILES (NVOX / V)

// Cross-launch accumulators. Zero at module load; the LAST block of every
// launch re-zeroes them after computing the loss, so every launch (and every
// graph replay) starts from zero. No separate zeroing kernel.
__device__ float g_sum[800];       // labels 1..50 x 16 ch
__device__ float g_nsum[800];
__device__ float g_cnt[50];        // label-1 indexed
__device__ unsigned g_done;

__global__ __launch_bounds__(256, 2) void k_main(const float* __restrict__ pred,
                                                 const int* __restrict__ gt,
                                                 float* __restrict__ out) {
    __shared__ __align__(16) float s_buf[V * STRIDEW];   // 40 KB
    __shared__ int s_hist[NUM_LABELS];
    __shared__ int s_base[NUM_LABELS];
    __shared__ float s_m[800], s_ns[800], s_c[50], s_in[50], s_acc[2];
    __shared__ int s_last;

    const int tid  = threadIdx.x;
    const int lane = tid & 31;
    const unsigned cmask = 0xFu << (lane & 28);

    float4 aS = make_float4(0.f, 0.f, 0.f, 0.f);
    float4 aN = make_float4(0.f, 0.f, 0.f, 0.f);
    int cntAcc = 0;

    if (tid < NUM_LABELS) s_hist[tid] = 0;
    __syncthreads();

    int rbase = 0, rcnt = 0;       // reduce params for the tile sitting in s_buf
    int havePrev = 0;

    const int g = tid & 3;         // channel group (reduce/flush role, tid<200)

    for (int tile = blockIdx.x; tile < NTILES; tile += NBLK) {
        int n0 = tile * V;

        // ---- 1) Issue ALL loads for THIS tile (latency covered by steps 2-4) ----
        int lab[VPT];
        float v[VPT][CH];
        #pragma unroll
        for (int k = 0; k < VPT; k++) {
            int n  = n0 + tid + k * 256;
            lab[k] = gt[n];                       // coalesced
            int bb = n >> 21;
            int sp = n & (SPATIAL - 1);
            const float* src = pred + ((long)bb << 25) + sp;
            #pragma unroll
            for (int c = 0; c < CH; c++)
                v[k][c] = src[(long)c << 21];     // coalesced per channel
        }

        // ---- 2) Reduce PREVIOUS tile from smem; idle threads zero hist ----
        if (havePrev && tid < 200 && rcnt > 0) {
            for (int j = 0; j < rcnt; j++) {
                int slot = rbase + j;
                const float4 v4 = *(const float4*)(s_buf + slot * STRIDEW
                                                   + (((g + slot) & 3) << 2));
                float ssq = v4.x * v4.x + v4.y * v4.y + v4.z * v4.z + v4.w * v4.w;
                ssq += __shfl_xor_sync(cmask, ssq, 1);
                ssq += __shfl_xor_sync(cmask, ssq, 2);
                float ri = rsqrtf(ssq);
                aS.x += v4.x;      aS.y += v4.y;      aS.z += v4.z;      aS.w += v4.w;
                aN.x += v4.x * ri; aN.y += v4.y * ri; aN.z += v4.z * ri; aN.w += v4.w * ri;
            }
        }
        if (tid >= 200 && tid - 200 < NUM_LABELS) s_hist[tid - 200] = 0;
        __syncthreads();

        // ---- 3) Rank THIS tile (gt arrived during reduce) ----
        int rnk[VPT];
        #pragma unroll
        for (int k = 0; k < VPT; k++) {
            bool valid = ((unsigned)(lab[k] - 1) <= 49u);
            int lv = valid ? lab[k] : -1;
            unsigned mask = __match_any_sync(0xffffffffu, lv);
            int leader = __ffs(mask) - 1;
            int rinw = __popc(mask & ((1u << lane) - 1u));
            int b = 0;
            if (lane == leader && valid) b = atomicAdd(&s_hist[lv], __popc(mask));
            b = __shfl_sync(0xffffffffu, b, leader);
            lab[k] = lv;
            rnk[k] = b + rinw;
        }
        __syncthreads();

        // ---- 4) Warp-shuffle exclusive scan (warp 0); capture; counts ----
        if (tid < 32) {
            int a = (tid < NUM_LABELS) ? s_hist[tid] : 0;
            int b = (tid + 32 < NUM_LABELS) ? s_hist[tid + 32] : 0;
            int sa = a, sb = b;
            #pragma unroll
            for (int d = 1; d < 32; d <<= 1) {
                int t1 = __shfl_up_sync(0xffffffffu, sa, d);
                int t2 = __shfl_up_sync(0xffffffffu, sb, d);
                if (lane >= d) { sa += t1; sb += t2; }
            }
            int totA = __shfl_sync(0xffffffffu, sa, 31);
            if (tid < NUM_LABELS) s_base[tid] = sa - a;
            if (tid + 32 < NUM_LABELS) s_base[tid + 32] = totA + sb - b;
        }
        __syncthreads();

        if (tid < 200) {
            int l = (tid >> 2) + 1;
            rbase = s_base[l];
            rcnt  = s_hist[l];
        }
        if (tid >= 33 && tid < 33 + 50) cntAcc += s_hist[tid - 32];

        // ---- 5) STS THIS tile label-sorted (v regs arrived long ago) ----
        #pragma unroll
        for (int k = 0; k < VPT; k++) {
            if (lab[k] > 0) {
                int slot = s_base[lab[k]] + rnk[k];
                int rot = slot & 3;
                float* d = s_buf + slot * STRIDEW;
                #pragma unroll
                for (int q = 0; q < 4; q++)
                    *(float4*)(d + (((q + rot) & 3) << 2)) =
                        make_float4(v[k][4*q], v[k][4*q+1], v[k][4*q+2], v[k][4*q+3]);
            }
        }
        __syncthreads();
        havePrev = 1;
    }

    // ---- Epilogue: reduce the final tile ----
    if (havePrev && tid < 200 && rcnt > 0) {
        for (int j = 0; j < rcnt; j++) {
            int slot = rbase + j;
            const float4 v4 = *(const float4*)(s_buf + slot * STRIDEW
                                               + (((g + slot) & 3) << 2));
            float ssq = v4.x * v4.x + v4.y * v4.y + v4.z * v4.z + v4.w * v4.w;
            ssq += __shfl_xor_sync(cmask, ssq, 1);
            ssq += __shfl_xor_sync(cmask, ssq, 2);
            float ri = rsqrtf(ssq);
            aS.x += v4.x;      aS.y += v4.y;      aS.z += v4.z;      aS.w += v4.w;
            aN.x += v4.x * ri; aN.y += v4.y * ri; aN.z += v4.z * ri; aN.w += v4.w * ri;
        }
    }

    // ---- Flush to global accumulators ----
    if (tid < 200) {
        int o = (tid >> 2) * CH + 4 * g;
        atomicAdd(&g_sum[o + 0], aS.x); atomicAdd(&g_sum[o + 1], aS.y);
        atomicAdd(&g_sum[o + 2], aS.z); atomicAdd(&g_sum[o + 3], aS.w);
        atomicAdd(&g_nsum[o + 0], aN.x); atomicAdd(&g_nsum[o + 1], aN.y);
        atomicAdd(&g_nsum[o + 2], aN.z); atomicAdd(&g_nsum[o + 3], aN.w);
    }
    if (tid >= 33 && tid < 33 + 50) atomicAdd(&g_cnt[tid - 33], (float)cntAcc);

    __threadfence();
    if (tid == 0) s_last = (atomicAdd(&g_done, 1u) == NBLK - 1);
    __syncthreads();
    if (!s_last) return;

    // ================= LAST BLOCK: finalize =================
    __threadfence();
    if (tid < 2) s_acc[tid] = 0.f;
    for (int i = tid; i < 800; i += 256) { s_m[i] = g_sum[i]; s_ns[i] = g_nsum[i]; }
    if (tid < 50) s_c[tid] = g_cnt[tid];
    __syncthreads();

    for (int i = tid; i < 800; i += 256)
        s_m[i] = s_m[i] / fmaxf(s_c[i >> 4], 1.f);
    __syncthreads();

    // intra_l = dot(m_l, nsum_l) / (|m_l| * count_l)
    if (tid < 50) {
        float n2 = 0.f;
        #pragma unroll
        for (int c = 0; c < 16; c++) { float m = s_m[tid * 16 + c]; n2 += m * m; }
        float nrm = sqrtf(n2);
        s_in[tid] = 1.f / fmaxf(nrm, EPSF);

        float dot = 0.f;
        #pragma unroll
        for (int c = 0; c < 16; c++) dot += s_m[tid * 16 + c] * s_ns[tid * 16 + c];
        float intra_l = dot / (fmaxf(nrm, 1e-30f) * fmaxf(s_c[tid], 1.f));
        atomicAdd(&s_acc[1], intra_l);
    }
    __syncthreads();

    for (int i = tid; i < 800; i += 256) s_m[i] *= s_in[i >> 4];
    __syncthreads();

    float local = 0.f;
    for (int pp = tid; pp < 1225; pp += 256) {
        int i = 0, rem = pp;
        while (rem >= 49 - i) { rem -= 49 - i; i++; }
        int j = i + 1 + rem;
        float dot = 0.f;
        #pragma unroll
        for (int c = 0; c < 16; c++) dot += s_m[i * 16 + c] * s_m[j * 16 + c];
        local += fminf(fmaxf(dot, 0.f), 1.f);
    }
    atomicAdd(&s_acc[0], local);
    __syncthreads();

    if (tid == 0) out[0] = s_acc[0] * (1.f / 1225.f) - s_acc[1] * (1.f / 50.f);

    // ---- Reset accumulators for the next launch / graph replay ----
    __syncthreads();
    for (int i = tid; i < 800; i += 256) { g_sum[i] = 0.f; g_nsum[i] = 0.f; }
    if (tid < 50) g_cnt[tid] = 0.f;
    if (tid == 0) g_done = 0u;
}

extern "C" void kernel_launch(void* const* d_in, const int* in_sizes, int n_in,
                              void* d_out, int out_size) {
    const float* pred = (const float*)d_in[0];
    const int* gt = (const int*)d_in[1];
    float* out = (float*)d_out;

    k_main<<<NBLK, 256>>>(pred, gt, out);
}